// round 2
// baseline (speedup 1.0000x reference)
#include <cuda_runtime.h>
#include <cuda_bf16.h>
#include <cstdint>
#include <math.h>

// Problem constants
#define BB 4
#define TT 512
#define DD 512
#define HH 1024
#define VV 50000
#define MROWS (BB*TT)          // 2048
#define G4H (4*HH)             // 4096
#define NB_REC 128             // recurrence grid blocks (all resident, 1 CTA/SM)
#define HC (HH/NB_REC)         // 8 h-cols per block
#define WPAD 1028              // padded row length (floats) for smem W / h

// ---------------- device scratch (static: no allocations allowed) -------------
__device__ __align__(256) __nv_bfloat16 g_emb [MROWS*DD];
__device__ __align__(256) __nv_bfloat16 g_Wih0[G4H*DD];
__device__ __align__(256) __nv_bfloat16 g_Wih1[G4H*HH];
__device__ __align__(256) __nv_bfloat16 g_Wout[VV*HH];
__device__ __align__(256) float         g_xg  [MROWS*G4H];
__device__ __align__(256) __nv_bfloat16 g_h0  [MROWS*HH];
__device__ __align__(256) __nv_bfloat16 g_h1  [MROWS*HH];
__device__ __align__(256) float         g_hbuf[2*BB*HH];
__device__ __align__(256) int           g_bar [TT];
__device__ __align__(256) float         g_rowoff[MROWS];

// ---------------- small helpers ----------------------------------------------
__device__ __forceinline__ int ld_cg_int(const int* p) {
    int v; asm volatile("ld.global.cg.b32 %0, [%1];" : "=r"(v) : "l"(p)); return v;
}
__device__ __forceinline__ uint32_t smem_u32(const void* p) {
    return (uint32_t)__cvta_generic_to_shared(p);
}
__device__ __forceinline__ void ldmatrix_x4(uint32_t r[4], uint32_t addr) {
    asm volatile("ldmatrix.sync.aligned.m8n8.x4.shared.b16 {%0,%1,%2,%3}, [%4];"
                 : "=r"(r[0]), "=r"(r[1]), "=r"(r[2]), "=r"(r[3]) : "r"(addr));
}
__device__ __forceinline__ void ldmatrix_x2(uint32_t r[2], uint32_t addr) {
    asm volatile("ldmatrix.sync.aligned.m8n8.x2.shared.b16 {%0,%1}, [%2];"
                 : "=r"(r[0]), "=r"(r[1]) : "r"(addr));
}
__device__ __forceinline__ void mma16816(float d[4], const uint32_t a[4],
                                         const uint32_t b[2], const float c[4]) {
    asm volatile(
        "mma.sync.aligned.m16n8k16.row.col.f32.bf16.bf16.f32 "
        "{%0,%1,%2,%3}, {%4,%5,%6,%7}, {%8,%9}, {%10,%11,%12,%13};"
        : "=f"(d[0]), "=f"(d[1]), "=f"(d[2]), "=f"(d[3])
        : "r"(a[0]), "r"(a[1]), "r"(a[2]), "r"(a[3]),
          "r"(b[0]), "r"(b[1]),
          "f"(c[0]), "f"(c[1]), "f"(c[2]), "f"(c[3]));
}

// ---------------- conversion / gather kernels ---------------------------------
__global__ void f32_to_bf16_k(const float* __restrict__ in,
                              __nv_bfloat16* __restrict__ out, int n4) {
    int i = blockIdx.x * blockDim.x + threadIdx.x;
    if (i >= n4) return;
    float4 v = *((const float4*)in + i);
    __nv_bfloat162 lo = __floats2bfloat162_rn(v.x, v.y);
    __nv_bfloat162 hi = __floats2bfloat162_rn(v.z, v.w);
    uint2 u;
    u.x = *(uint32_t*)&lo; u.y = *(uint32_t*)&hi;
    *((uint2*)out + i) = u;
}

__global__ void gather_embed_k(const int* __restrict__ idx,
                               const float* __restrict__ X) {
    int i = blockIdx.x * blockDim.x + threadIdx.x;   // one float4 each
    if (i >= MROWS * (DD/4)) return;
    int r = i >> 7;             // DD/4 = 128
    int j = i & 127;
    int tok = __ldg(&idx[r]);
    float4 v = *(const float4*)(X + (size_t)tok * DD + j * 4);
    __nv_bfloat162 lo = __floats2bfloat162_rn(v.x, v.y);
    __nv_bfloat162 hi = __floats2bfloat162_rn(v.z, v.w);
    uint2 u; u.x = *(uint32_t*)&lo; u.y = *(uint32_t*)&hi;
    *((uint2*)(g_emb + (size_t)r * DD) + j) = u;
}

__global__ void zero_hbuf_k() {
    int i = blockIdx.x * blockDim.x + threadIdx.x;
    if (i < 2*BB*HH) g_hbuf[i] = 0.f;
}

// ---------------- bf16 MMA GEMM: C[M,N] = A[M,K] * B[N,K]^T + bias ------------
// CTA tile 128x128, K-tile 32, 8 warps (2 M x 4 N), warp tile 64x32.
__global__ __launch_bounds__(256) void gemm_bf16_k(
    const __nv_bfloat16* __restrict__ A, const __nv_bfloat16* __restrict__ B,
    const float* __restrict__ bias, float* __restrict__ C,
    int M, int N, int K)
{
    __shared__ __nv_bfloat16 As[128][40];
    __shared__ __nv_bfloat16 Bs[128][40];

    const int tid  = threadIdx.x;
    const int warp = tid >> 5, lane = tid & 31;
    const int wm = warp & 1, wn = warp >> 1;
    const int m0 = blockIdx.y * 128, n0 = blockIdx.x * 128;

    float acc[4][4][4];
#pragma unroll
    for (int a = 0; a < 4; a++)
#pragma unroll
        for (int b = 0; b < 4; b++)
#pragma unroll
            for (int c = 0; c < 4; c++) acc[a][b][c] = 0.f;

    const int ktiles = K >> 5;
    for (int kt = 0; kt < ktiles; kt++) {
        const int k0 = kt << 5;
#pragma unroll
        for (int i = 0; i < 2; i++) {
            int c = tid + i * 256;
            int row = c >> 2;
            int kc  = (c & 3) << 3;
            uint4 va = *(const uint4*)(A + (size_t)(m0 + row) * K + k0 + kc);
            *(uint4*)&As[row][kc] = va;
            int gn = n0 + row;
            uint4 vb = make_uint4(0u, 0u, 0u, 0u);
            if (gn < N) vb = *(const uint4*)(B + (size_t)gn * K + k0 + kc);
            *(uint4*)&Bs[row][kc] = vb;
        }
        __syncthreads();

#pragma unroll
        for (int ks = 0; ks < 2; ks++) {
            uint32_t af[4][4], bf[4][2];
#pragma unroll
            for (int mt = 0; mt < 4; mt++) {
                uint32_t addr = smem_u32(
                    &As[wm*64 + mt*16 + (lane & 15)][ks*16 + ((lane >> 4) << 3)]);
                ldmatrix_x4(af[mt], addr);
            }
#pragma unroll
            for (int nt = 0; nt < 4; nt++) {
                uint32_t addr = smem_u32(
                    &Bs[wn*32 + nt*8 + (lane & 7)][ks*16 + (((lane >> 3) & 1) << 3)]);
                ldmatrix_x2(bf[nt], addr);
            }
#pragma unroll
            for (int mt = 0; mt < 4; mt++)
#pragma unroll
                for (int nt = 0; nt < 4; nt++)
                    mma16816(acc[mt][nt], af[mt], bf[nt], acc[mt][nt]);
        }
        __syncthreads();
    }

#pragma unroll
    for (int mt = 0; mt < 4; mt++)
#pragma unroll
        for (int nt = 0; nt < 4; nt++)
#pragma unroll
            for (int i = 0; i < 4; i++) {
                int row = m0 + wm*64 + mt*16 + (lane >> 2) + ((i >> 1) << 3);
                int col = n0 + wn*32 + nt*8 + ((lane & 3) << 1) + (i & 1);
                if (col < N)
                    C[(size_t)row * N + col] = acc[mt][nt][i] + __ldg(&bias[col]);
            }
}

// ---------------- persistent LSTM recurrence ----------------------------------
// Grid = 128 CTAs (all resident, 1 CTA/SM at 146KB smem). Block bk owns 8
// h-columns, keeps its 32 W_hh rows (i,f,g,o) in SMEM across all 512 steps.
// Grid barrier = slot array g_bar[t]; block 0 clears slot t-1 after passing
// barrier t, and clears the stale slot T-1 at kernel start (safe: no CTA can
// reach barrier T-1 before block 0 has passed barriers 0..T-2).
#define REC_SMEM_FLOATS (32*WPAD + 4*WPAD + 256 + 128 + 32)
#define REC_SMEM_BYTES  (REC_SMEM_FLOATS * 4)

__global__ void lstm_rec_k(const float* __restrict__ xg,
                           const float* __restrict__ Whh,
                           __nv_bfloat16* __restrict__ hseq)
{
    extern __shared__ float sm[];
    float* Wsm     = sm;                    // [32][WPAD]
    float* hsm     = Wsm + 32*WPAD;         // [4][WPAD]
    float* partial = hsm + 4*WPAD;          // [256]
    float* gsm     = partial + 256;         // [128]
    float* csm     = gsm + 128;             // [32]

    const int tid = threadIdx.x;
    const int bk  = blockIdx.x;
    const int c0  = bk * HC;

    if (bk == 0 && tid == 0) { atomicExch(&g_bar[TT-1], 0); __threadfence(); }

    // load the 32 W_hh rows this block needs
    for (int i = tid; i < 32*256; i += 256) {
        int lr = i >> 8;
        int kc = (i & 255) << 2;
        int gate = lr >> 3, ci = lr & 7;
        int grow = gate * HH + c0 + ci;
        float4 v = *(const float4*)(Whh + (size_t)grow * HH + kc);
        *(float4*)&Wsm[lr*WPAD + kc] = v;
    }
    if (tid < 32) csm[tid] = 0.f;
    __syncthreads();

    const int kh  = tid >> 7;       // half of K
    const int idx = tid & 127;
    const int bI  = idx & 3;
    const int lr  = idx >> 2;
    const float* wrow = Wsm + lr*WPAD + kh*512;

    for (int t = 0; t < TT; t++) {
        // fetch h_{t-1} (L2, bypass L1: written by other CTAs)
        const float* hsrc = g_hbuf + (t & 1) * BB * HH;
        for (int i = tid; i < BB*HH/4; i += 256) {
            int b  = i >> 8;
            int kc = (i & 255) << 2;
            float4 v = __ldcg((const float4*)(hsrc + b*HH + kc));
            *(float4*)&hsm[b*WPAD + kc] = v;
        }
        __syncthreads();

        // partial dot: gate row lr, batch bI, k-half kh
        const float* hrow = hsm + bI*WPAD + kh*512;
        float ax = 0.f, ay = 0.f, az = 0.f, aw = 0.f;
#pragma unroll 8
        for (int k = 0; k < 512; k += 4) {
            float4 w = *(const float4*)(wrow + k);
            float4 h = *(const float4*)(hrow + k);
            ax = fmaf(w.x, h.x, ax);
            ay = fmaf(w.y, h.y, ay);
            az = fmaf(w.z, h.z, az);
            aw = fmaf(w.w, h.w, aw);
        }
        partial[tid] = (ax + ay) + (az + aw);
        __syncthreads();

        if (tid < 128) {
            int gate = lr >> 3, ci = lr & 7;
            float g = partial[tid] + partial[tid + 128]
                    + __ldg(&xg[(size_t)(bI*TT + t) * G4H + gate*HH + c0 + ci]);
            gsm[tid] = g;
        }
        __syncthreads();

        if (tid < 32) {
            int ci = tid >> 2, b = tid & 3;
            float iv = gsm[((0*8 + ci) << 2) + b];
            float fv = gsm[((1*8 + ci) << 2) + b];
            float gv = gsm[((2*8 + ci) << 2) + b];
            float ov = gsm[((3*8 + ci) << 2) + b];
            iv = 1.f / (1.f + __expf(-iv));
            fv = 1.f / (1.f + __expf(-fv));
            gv = tanhf(gv);
            ov = 1.f / (1.f + __expf(-ov));
            float c = fv * csm[tid] + iv * gv;
            csm[tid] = c;
            float h = ov * tanhf(c);
            g_hbuf[((t + 1) & 1) * BB * HH + b * HH + c0 + ci] = h;
            hseq[(size_t)(b*TT + t) * HH + c0 + ci] = __float2bfloat16(h);
        }
        __threadfence();
        __syncthreads();

        if (tid == 0) {
            atomicAdd(&g_bar[t], 1);
            while (ld_cg_int(&g_bar[t]) < NB_REC) { }
            if (bk == 0 && t > 0) atomicExch(&g_bar[t - 1], 0);
        }
        __syncthreads();
    }
}

// ---------------- log-softmax -------------------------------------------------
__global__ void rowstats_k(const float* __restrict__ C) {
    __shared__ float red[256];
    const int row = blockIdx.x;
    const int tid = threadIdx.x;
    const float4* p = (const float4*)(C + (size_t)row * VV);
    const int n4 = VV / 4;   // 12500

    float m = -1e30f;
    for (int i = tid; i < n4; i += 256) {
        float4 v = p[i];
        m = fmaxf(m, fmaxf(fmaxf(v.x, v.y), fmaxf(v.z, v.w)));
    }
    red[tid] = m; __syncthreads();
    for (int s = 128; s > 0; s >>= 1) {
        if (tid < s) red[tid] = fmaxf(red[tid], red[tid + s]);
        __syncthreads();
    }
    m = red[0]; __syncthreads();

    float sum = 0.f;
    for (int i = tid; i < n4; i += 256) {
        float4 v = p[i];
        sum += __expf(v.x - m) + __expf(v.y - m) + __expf(v.z - m) + __expf(v.w - m);
    }
    red[tid] = sum; __syncthreads();
    for (int s = 128; s > 0; s >>= 1) {
        if (tid < s) red[tid] += red[tid + s];
        __syncthreads();
    }
    if (tid == 0) g_rowoff[row] = m + logf(red[0]);
}

__global__ void logsm_apply_k(float* __restrict__ C) {
    const int row = blockIdx.y;
    const int i = blockIdx.x * blockDim.x + threadIdx.x;
    if (i >= VV/4) return;
    float4* p = (float4*)(C + (size_t)row * VV);
    float off = __ldg(&g_rowoff[row]);
    float4 v = p[i];
    v.x -= off; v.y -= off; v.z -= off; v.w -= off;
    p[i] = v;
}

// ---------------- launcher ----------------------------------------------------
extern "C" void kernel_launch(void* const* d_in, const int* in_sizes, int n_in,
                              void* d_out, int out_size) {
    const int*   token_idx = (const int*)  d_in[0];
    const float* X     = (const float*)d_in[1];
    const float* W_ih0 = (const float*)d_in[2];
    const float* W_hh0 = (const float*)d_in[3];
    const float* b0    = (const float*)d_in[4];
    const float* W_ih1 = (const float*)d_in[5];
    const float* W_hh1 = (const float*)d_in[6];
    const float* b1    = (const float*)d_in[7];
    const float* W_out = (const float*)d_in[8];
    const float* b_out = (const float*)d_in[9];
    float* out = (float*)d_out;

    cudaFuncSetAttribute(lstm_rec_k,
                         cudaFuncAttributeMaxDynamicSharedMemorySize,
                         REC_SMEM_BYTES);

    void *p_emb, *p_Wih0, *p_Wih1, *p_Wout, *p_xg, *p_h0, *p_h1;
    cudaGetSymbolAddress(&p_emb,  g_emb);
    cudaGetSymbolAddress(&p_Wih0, g_Wih0);
    cudaGetSymbolAddress(&p_Wih1, g_Wih1);
    cudaGetSymbolAddress(&p_Wout, g_Wout);
    cudaGetSymbolAddress(&p_xg,   g_xg);
    cudaGetSymbolAddress(&p_h0,   g_h0);
    cudaGetSymbolAddress(&p_h1,   g_h1);

    // 1. embedding gather -> bf16, weight conversions -> bf16
    gather_embed_k<<<(MROWS*(DD/4) + 255)/256, 256>>>(token_idx, X);
    f32_to_bf16_k<<<(G4H*DD/4  + 255)/256, 256>>>(W_ih0, (__nv_bfloat16*)p_Wih0, G4H*DD/4);
    f32_to_bf16_k<<<(G4H*HH/4  + 255)/256, 256>>>(W_ih1, (__nv_bfloat16*)p_Wih1, G4H*HH/4);
    f32_to_bf16_k<<<(VV*HH/4   + 255)/256, 256>>>(W_out, (__nv_bfloat16*)p_Wout, VV*HH/4);

    // 2. layer-0 input GEMM: xg = emb @ W_ih0^T + b0
    gemm_bf16_k<<<dim3(G4H/128, MROWS/128), 256>>>(
        (const __nv_bfloat16*)p_emb, (const __nv_bfloat16*)p_Wih0, b0,
        (float*)p_xg, MROWS, G4H, DD);

    // 3. layer-0 recurrence
    zero_hbuf_k<<<(2*BB*HH + 255)/256, 256>>>();
    lstm_rec_k<<<NB_REC, 256, REC_SMEM_BYTES>>>(
        (const float*)p_xg, W_hh0, (__nv_bfloat16*)p_h0);

    // 4. layer-1 input GEMM: xg = h0 @ W_ih1^T + b1
    gemm_bf16_k<<<dim3(G4H/128, MROWS/128), 256>>>(
        (const __nv_bfloat16*)p_h0, (const __nv_bfloat16*)p_Wih1, b1,
        (float*)p_xg, MROWS, G4H, HH);

    // 5. layer-1 recurrence
    zero_hbuf_k<<<(2*BB*HH + 255)/256, 256>>>();
    lstm_rec_k<<<NB_REC, 256, REC_SMEM_BYTES>>>(
        (const float*)p_xg, W_hh1, (__nv_bfloat16*)p_h1);

    // 6. output GEMM: logits = h1 @ W_out^T + b_out  (written to d_out)
    gemm_bf16_k<<<dim3((VV + 127)/128, MROWS/128), 256>>>(
        (const __nv_bfloat16*)p_h1, (const __nv_bfloat16*)p_Wout, b_out,
        out, MROWS, VV, HH);

    // 7. log_softmax over V
    rowstats_k<<<MROWS, 256>>>(out);
    logsm_apply_k<<<dim3((VV/4 + 255)/256, MROWS), 256>>>(out);
}